// round 1
// baseline (speedup 1.0000x reference)
#include <cuda_runtime.h>
#include <cuda_bf16.h>
#include <math.h>

// ---------------- Problem constants ----------------
#define BB 4
#define LL 2048
#define DMODEL 1024
#define DINNER 2048
#define DSTATE 32
#define DTRANK 64
#define DCONV 4
#define MM (BB*LL)          // 8192 rows
#define XPROJ_N (DTRANK + 2*DSTATE)  // 128

// ---------------- Scratch (device globals; no allocation allowed) ----------------
__device__ float g_xn [MM*DMODEL];      // rmsnorm output
__device__ float g_xz [MM*(2*DINNER)];  // in_proj output: [:,0:2048]=u, [:,2048:4096]=z
__device__ float g_uc [MM*DINNER];      // silu(conv(u))
__device__ float g_dbl[MM*XPROJ_N];     // x_proj output: [0:64)=dt_r, [64:96)=B, [96:128)=C
__device__ float g_dt [MM*DINNER];      // softplus(dt_r @ dt_proj_w^T + b)
__device__ float g_y  [MM*DINNER];      // gated scan output

// ---------------- RMSNorm: one CTA(256) per row of 1024 ----------------
__global__ __launch_bounds__(256) void rmsnorm_kernel(
    const float* __restrict__ x, const float* __restrict__ w, float* __restrict__ xn)
{
    __shared__ float red[8];
    __shared__ float s_scale;
    int m = blockIdx.x, tid = threadIdx.x;
    float4 v = reinterpret_cast<const float4*>(x + (size_t)m*DMODEL)[tid];
    float s = v.x*v.x + v.y*v.y + v.z*v.z + v.w*v.w;
    #pragma unroll
    for (int o = 16; o > 0; o >>= 1) s += __shfl_xor_sync(0xffffffffu, s, o);
    if ((tid & 31) == 0) red[tid >> 5] = s;
    __syncthreads();
    if (tid < 32) {
        float t = (tid < 8) ? red[tid] : 0.f;
        #pragma unroll
        for (int o = 4; o > 0; o >>= 1) t += __shfl_xor_sync(0xffffffffu, t, o);
        if (tid == 0) s_scale = rsqrtf(t * (1.0f/DMODEL) + 1e-6f);
    }
    __syncthreads();
    float sc = s_scale;
    float4 wv = reinterpret_cast<const float4*>(w)[tid];
    float4 o;
    o.x = v.x*sc*wv.x; o.y = v.y*sc*wv.y; o.z = v.z*sc*wv.z; o.w = v.w*sc*wv.w;
    reinterpret_cast<float4*>(xn + (size_t)m*DMODEL)[tid] = o;
}

// ---------------- Generic NT SGEMM: C[m,n] = sum_k A[m,k]*Bw[n,k] (+epilogue) ----------
// A: M x K (row stride lda), Bw: N x K row-major (weights), C: M x N dense.
// EPI: 0 = none, 1 = softplus(acc + bias[n]), 2 = acc + resid[m*N+n]
template<int BM, int BN, int BK, int TM, int TN, int EPI>
__global__ __launch_bounds__((BM/TM)*(BN/TN)) void gemm_kernel(
    const float* __restrict__ A, int lda,
    const float* __restrict__ Bw,
    float* __restrict__ C,
    int M, int N, int K,
    const float* __restrict__ bias,
    const float* __restrict__ resid)
{
    constexpr int THREADS = (BM/TM)*(BN/TN);
    static_assert((BM*BK/4) == THREADS, "one float4 per thread per tile");
    static_assert(BM == BN, "load symmetry");
    __shared__ float As[BK][BM];
    __shared__ float Bs[BK][BN];

    const int tid  = threadIdx.x;
    const int m0   = blockIdx.y * BM;
    const int n0   = blockIdx.x * BN;
    constexpr int AV = BK/4;
    const int arow = tid / AV;
    const int acol = (tid % AV) * 4;
    const int tcol = tid % (BN/TN);
    const int trow = tid / (BN/TN);

    const float* Ap = A  + (size_t)(m0 + arow) * lda + acol;
    const float* Bp = Bw + (size_t)(n0 + arow) * K   + acol;

    float acc[TM][TN];
    #pragma unroll
    for (int i = 0; i < TM; ++i)
        #pragma unroll
        for (int j = 0; j < TN; ++j) acc[i][j] = 0.f;

    for (int k0 = 0; k0 < K; k0 += BK) {
        float4 av = *reinterpret_cast<const float4*>(Ap + k0);
        float4 bv = *reinterpret_cast<const float4*>(Bp + k0);
        As[acol+0][arow] = av.x; As[acol+1][arow] = av.y;
        As[acol+2][arow] = av.z; As[acol+3][arow] = av.w;
        Bs[acol+0][arow] = bv.x; Bs[acol+1][arow] = bv.y;
        Bs[acol+2][arow] = bv.z; Bs[acol+3][arow] = bv.w;
        __syncthreads();
        #pragma unroll
        for (int kk = 0; kk < BK; ++kk) {
            float ra[TM], rb[TN];
            #pragma unroll
            for (int i = 0; i < TM; ++i) ra[i] = As[kk][trow*TM + i];
            #pragma unroll
            for (int j = 0; j < TN; ++j) rb[j] = Bs[kk][tcol*TN + j];
            #pragma unroll
            for (int i = 0; i < TM; ++i)
                #pragma unroll
                for (int j = 0; j < TN; ++j) acc[i][j] = fmaf(ra[i], rb[j], acc[i][j]);
        }
        __syncthreads();
    }

    #pragma unroll
    for (int i = 0; i < TM; ++i) {
        const int m = m0 + trow*TM + i;
        #pragma unroll
        for (int j4 = 0; j4 < TN; j4 += 4) {
            float4 o;
            float* po = &o.x;
            #pragma unroll
            for (int q = 0; q < 4; ++q) {
                const int n = n0 + tcol*TN + j4 + q;
                float v = acc[i][j4+q];
                if (EPI == 1) {
                    float t = v + bias[n];
                    v = (t > 20.f) ? t : log1pf(__expf(t));
                } else if (EPI == 2) {
                    v += resid[(size_t)m*N + n];
                }
                po[q] = v;
            }
            *reinterpret_cast<float4*>(C + (size_t)m*N + n0 + tcol*TN + j4) = o;
        }
    }
}

// ---------------- Depthwise causal conv (k=4) + bias + SiLU ----------------
__global__ __launch_bounds__(256) void conv_silu_kernel(
    const float* __restrict__ xz, const float* __restrict__ cw,
    const float* __restrict__ cb, float* __restrict__ uc)
{
    int idx = blockIdx.x * 256 + threadIdx.x;           // m*DINNER + d, total 16.8M
    int d = idx & (DINNER-1);
    int m = idx >> 11;                                  // DINNER = 2^11
    int l = m & (LL-1);                                 // LL = 2^11 (within-batch index)
    float4 wv = reinterpret_cast<const float4*>(cw)[d]; // conv_w[d][0..3]
    const float* up = xz + (size_t)m * (2*DINNER) + d;  // u part, row stride 4096
    float acc = cb[d];
    acc = fmaf(up[0], wv.w, acc);                                     // j=3 -> u[l]
    if (l >= 1) acc = fmaf(up[-1*(2*DINNER)], wv.z, acc);             // j=2 -> u[l-1]
    if (l >= 2) acc = fmaf(up[-2*(2*DINNER)], wv.y, acc);             // j=1 -> u[l-2]
    if (l >= 3) acc = fmaf(up[-3*(2*DINNER)], wv.x, acc);             // j=0 -> u[l-3]
    uc[idx] = acc / (1.f + __expf(-acc)) ;                            // silu
}

// ---------------- Selective scan: warp = one (b,d), lane = state n ----------------
// CTA: 256 thr = 8 warps = 8 channels; chunks of 64 timesteps staged in smem.
#define SCL 64   // chunk length
#define SWP 8    // warps (channels) per CTA
__global__ __launch_bounds__(256) void scan_kernel(
    const float* __restrict__ xz,  const float* __restrict__ uc,
    const float* __restrict__ dbl, const float* __restrict__ dt,
    const float* __restrict__ A_log, const float* __restrict__ D_param,
    float* __restrict__ y)
{
    __shared__ float sB [SCL][DSTATE];
    __shared__ float sC [SCL][DSTATE];
    __shared__ float sdt[SCL][SWP];
    __shared__ float su [SCL][SWP];
    __shared__ float sz [SCL][SWP];
    __shared__ float sy [SCL][SWP];

    const int b    = blockIdx.y;
    const int d0   = blockIdx.x * SWP;
    const int tid  = threadIdx.x;
    const int w    = tid >> 5;
    const int lane = tid & 31;
    const int d    = d0 + w;
    const int mb   = b * LL;

    const float Aln = -__expf(A_log[d*DSTATE + lane]);
    const float Dd  = D_param[d];
    float h = 0.f;

    for (int c0 = 0; c0 < LL; c0 += SCL) {
        // stage B, C (shared across channels)
        for (int idx = tid; idx < SCL*DSTATE; idx += 256) {
            int t = idx >> 5, n = idx & 31;
            int m = mb + c0 + t;
            sB[t][n] = dbl[(size_t)m*XPROJ_N + DTRANK + n];
            sC[t][n] = dbl[(size_t)m*XPROJ_N + DTRANK + DSTATE + n];
        }
        // stage per-channel scalars: dt, u, z
        for (int idx = tid; idx < SCL*SWP; idx += 256) {
            int t = idx >> 3, dd = idx & 7;
            int m = mb + c0 + t;
            sdt[t][dd] = dt[(size_t)m*DINNER + d0 + dd];
            su [t][dd] = uc[(size_t)m*DINNER + d0 + dd];
            sz [t][dd] = xz[(size_t)m*(2*DINNER) + DINNER + d0 + dd];
        }
        __syncthreads();

        #pragma unroll 4
        for (int t = 0; t < SCL; ++t) {
            float dtv = sdt[t][w];
            float uv  = su[t][w];
            float dA  = __expf(dtv * Aln);
            h = fmaf(dA, h, (dtv * uv) * sB[t][lane]);
            float p = h * sC[t][lane];
            p += __shfl_xor_sync(0xffffffffu, p, 16);
            p += __shfl_xor_sync(0xffffffffu, p, 8);
            p += __shfl_xor_sync(0xffffffffu, p, 4);
            p += __shfl_xor_sync(0xffffffffu, p, 2);
            p += __shfl_xor_sync(0xffffffffu, p, 1);
            if (lane == 0) {
                float yv = p + uv * Dd;
                float zv = sz[t][w];
                sy[t][w] = yv * (zv / (1.f + __expf(-zv)));
            }
        }
        __syncthreads();

        // write y chunk coalesced
        for (int idx = tid; idx < SCL*SWP; idx += 256) {
            int t = idx >> 3, dd = idx & 7;
            y[(size_t)(mb + c0 + t)*DINNER + d0 + dd] = sy[t][dd];
        }
        // next iteration's staging writes are fenced by the post-load __syncthreads;
        // staging vs compute handled by the two syncs above (store touches only sy / gmem)
    }
}

// ---------------- Launch ----------------
extern "C" void kernel_launch(void* const* d_in, const int* in_sizes, int n_in,
                              void* d_out, int out_size)
{
    const float* x         = (const float*)d_in[0];
    const float* norm_w    = (const float*)d_in[1];
    const float* in_proj_w = (const float*)d_in[2];
    const float* conv_w    = (const float*)d_in[3];
    const float* conv_b    = (const float*)d_in[4];
    const float* x_proj_w  = (const float*)d_in[5];
    const float* dt_proj_w = (const float*)d_in[6];
    const float* dt_proj_b = (const float*)d_in[7];
    const float* A_log     = (const float*)d_in[8];
    const float* D_param   = (const float*)d_in[9];
    const float* out_proj_w= (const float*)d_in[10];
    float* out = (float*)d_out;

    static float *p_xn = nullptr, *p_xz, *p_uc, *p_dbl, *p_dt, *p_y;
    if (!p_xn) {
        cudaGetSymbolAddress((void**)&p_xn,  g_xn);
        cudaGetSymbolAddress((void**)&p_xz,  g_xz);
        cudaGetSymbolAddress((void**)&p_uc,  g_uc);
        cudaGetSymbolAddress((void**)&p_dbl, g_dbl);
        cudaGetSymbolAddress((void**)&p_dt,  g_dt);
        cudaGetSymbolAddress((void**)&p_y,   g_y);
    }

    // 1) RMSNorm
    rmsnorm_kernel<<<MM, 256>>>(x, norm_w, p_xn);

    // 2) in_proj: xz[8192,4096] = xn @ in_proj_w^T
    gemm_kernel<128,128,8,8,8,0><<<dim3((2*DINNER)/128, MM/128), 256>>>(
        p_xn, DMODEL, in_proj_w, p_xz, MM, 2*DINNER, DMODEL, nullptr, nullptr);

    // 3) conv + silu on u half of xz
    conv_silu_kernel<<<(MM*DINNER)/256, 256>>>(p_xz, conv_w, conv_b, p_uc);

    // 4) x_proj: dbl[8192,128] = uc @ x_proj_w^T
    gemm_kernel<64,64,16,4,4,0><<<dim3(XPROJ_N/64, MM/64), 256>>>(
        p_uc, DINNER, x_proj_w, p_dbl, MM, XPROJ_N, DINNER, nullptr, nullptr);

    // 5) dt_proj + softplus: dt[8192,2048] (A = first 64 cols of dbl, lda=128)
    gemm_kernel<128,128,8,8,8,1><<<dim3(DINNER/128, MM/128), 256>>>(
        p_dbl, XPROJ_N, dt_proj_w, p_dt, MM, DINNER, DTRANK, dt_proj_b, nullptr);

    // 6) selective scan + skip (u*D) + silu(z) gating -> y
    scan_kernel<<<dim3(DINNER/SWP, BB), 256>>>(
        p_xz, p_uc, p_dbl, p_dt, A_log, D_param, p_y);

    // 7) out_proj + residual: out = x + y @ out_proj_w^T
    gemm_kernel<128,128,8,8,8,2><<<dim3(DMODEL/128, MM/128), 256>>>(
        p_y, DINNER, out_proj_w, out, MM, DMODEL, DINNER, nullptr, x);
}

// round 6
// speedup vs baseline: 1.9848x; 1.9848x over previous
#include <cuda_runtime.h>
#include <cuda_bf16.h>
#include <math.h>
#include <stdint.h>

// ---------------- Problem constants ----------------
#define BB 4
#define LL 2048
#define DMODEL 1024
#define DINNER 2048
#define DSTATE 32
#define DTRANK 64
#define MM (BB*LL)          // 8192 rows
#define XPROJ_N 128

// ---------------- Scratch ----------------
__device__ float g_xn [MM*DMODEL];
__device__ float g_xz [MM*(2*DINNER)];
__device__ float g_uc [MM*DINNER];
__device__ float g_dbl[MM*XPROJ_N];
__device__ float g_dt [MM*DINNER];
__device__ float g_y  [MM*DINNER];

// ---------------- helpers ----------------
__device__ __forceinline__ uint32_t smem_u32(const void* p){
    uint32_t a;
    asm("{ .reg .u64 t; cvta.to.shared.u64 t, %1; cvt.u32.u64 %0, t; }" : "=r"(a) : "l"(p));
    return a;
}
__device__ __forceinline__ uint32_t f2tf(float f){
    uint32_t r; asm("cvt.rna.tf32.f32 %0, %1;" : "=r"(r) : "f"(f)); return r;
}
__device__ __forceinline__ void mma_tf32(float* c, const uint32_t* a, const uint32_t* b){
    asm volatile(
        "mma.sync.aligned.m16n8k8.row.col.f32.tf32.tf32.f32 "
        "{%0,%1,%2,%3}, {%4,%5,%6,%7}, {%8,%9}, {%0,%1,%2,%3};"
        : "+f"(c[0]), "+f"(c[1]), "+f"(c[2]), "+f"(c[3])
        : "r"(a[0]), "r"(a[1]), "r"(a[2]), "r"(a[3]), "r"(b[0]), "r"(b[1]));
}

// ---------------- tf32 mma.sync GEMM ----------------
// C[m,n] = sum_k A[m,k]*Bw[n,k]; A row-major lda, Bw row-major [N,K].
// BM=BN=128, BK=32. 256 threads = 8 warps (2 m x 4 n), warp tile 64x32.
// EPI: 0 none, 1 softplus(acc+bias[n]), 2 acc+resid[m*N+n]
#define GP 36                      // smem row pitch in floats
#define TILE_ROW_BYTES (GP*4)      // 144
#define SA_BYTES (128*TILE_ROW_BYTES)       // 18432
#define STAGE_BYTES (2*SA_BYTES)            // 36864 (A then B)
#define SMEM_TOTAL (2*STAGE_BYTES)          // 73728

template<int EPI>
__global__ __launch_bounds__(256, 2) void mma_gemm(
    const float* __restrict__ A, int lda,
    const float* __restrict__ Bw,
    float* __restrict__ C,
    int N, int K,
    const float* __restrict__ bias,
    const float* __restrict__ resid)
{
    extern __shared__ char dynsmem[];
    float* sm = reinterpret_cast<float*>(dynsmem);
    const uint32_t sm32 = smem_u32(dynsmem);

    const int tid  = threadIdx.x;
    const int wid  = tid >> 5, lane = tid & 31;
    const int g    = lane >> 2;        // 0..7
    const int c    = lane & 3;         // 0..3
    const int wm   = (wid >> 2) * 64;  // warp m offset
    const int wn   = (wid & 3) * 32;   // warp n offset
    const int m0   = blockIdx.y * 128;
    const int n0   = blockIdx.x * 128;

    // gmem->smem assignment: row = tid/8 (+32*i), kquad = tid%8
    const int lrow = tid >> 3;
    const int lk16 = (tid & 7) * 16;   // byte offset within 128B of row data

    const float* Ap0 = A  + (size_t)(m0 + lrow) * lda + (lk16 >> 2);
    const float* Bp0 = Bw + (size_t)(n0 + lrow) * K   + (lk16 >> 2);

    float acc[4][4][4];
    #pragma unroll
    for (int i = 0; i < 4; ++i)
        #pragma unroll
        for (int j = 0; j < 4; ++j)
            #pragma unroll
            for (int q = 0; q < 4; ++q) acc[i][j][q] = 0.f;

    const int KT = K / 32;

    // prologue: load tile 0 into stage 0
    {
        const uint32_t da = sm32;
        const uint32_t db = sm32 + SA_BYTES;
        #pragma unroll
        for (int i = 0; i < 4; ++i) {
            asm volatile("cp.async.cg.shared.global [%0], [%1], 16;"
                :: "r"(da + (lrow + 32*i)*TILE_ROW_BYTES + lk16),
                   "l"(Ap0 + (size_t)(32*i)*lda));
            asm volatile("cp.async.cg.shared.global [%0], [%1], 16;"
                :: "r"(db + (lrow + 32*i)*TILE_ROW_BYTES + lk16),
                   "l"(Bp0 + (size_t)(32*i)*K));
        }
        asm volatile("cp.async.commit_group;" ::: "memory");
    }

    for (int kt = 0; kt < KT; ++kt) {
        const int s = kt & 1;
        // prefetch next tile into other stage
        if (kt + 1 < KT) {
            const uint32_t da = sm32 + (1 - s)*STAGE_BYTES;
            const uint32_t db = da + SA_BYTES;
            const float* Apn = Ap0 + (kt + 1)*32;
            const float* Bpn = Bp0 + (kt + 1)*32;
            #pragma unroll
            for (int i = 0; i < 4; ++i) {
                asm volatile("cp.async.cg.shared.global [%0], [%1], 16;"
                    :: "r"(da + (lrow + 32*i)*TILE_ROW_BYTES + lk16),
                       "l"(Apn + (size_t)(32*i)*lda));
                asm volatile("cp.async.cg.shared.global [%0], [%1], 16;"
                    :: "r"(db + (lrow + 32*i)*TILE_ROW_BYTES + lk16),
                       "l"(Bpn + (size_t)(32*i)*K));
            }
            asm volatile("cp.async.commit_group;" ::: "memory");
            asm volatile("cp.async.wait_group 1;" ::: "memory");
        } else {
            asm volatile("cp.async.wait_group 0;" ::: "memory");
        }
        __syncthreads();

        // compute from stage s
        const float* sA = sm + (s*STAGE_BYTES >> 2);
        const float* sB = sA + (SA_BYTES >> 2);
        #pragma unroll
        for (int k8 = 0; k8 < 4; ++k8) {
            const int kb = k8 * 8;
            uint32_t afr[4][4];
            #pragma unroll
            for (int mt = 0; mt < 4; ++mt) {
                const int row = wm + mt*16 + g;
                afr[mt][0] = f2tf(sA[row*GP + kb + c]);
                afr[mt][1] = f2tf(sA[(row+8)*GP + kb + c]);
                afr[mt][2] = f2tf(sA[row*GP + kb + c + 4]);
                afr[mt][3] = f2tf(sA[(row+8)*GP + kb + c + 4]);
            }
            uint32_t bfr[4][2];
            #pragma unroll
            for (int nt = 0; nt < 4; ++nt) {
                const int nr = wn + nt*8 + g;
                bfr[nt][0] = f2tf(sB[nr*GP + kb + c]);
                bfr[nt][1] = f2tf(sB[nr*GP + kb + c + 4]);
            }
            #pragma unroll
            for (int mt = 0; mt < 4; ++mt)
                #pragma unroll
                for (int nt = 0; nt < 4; ++nt)
                    mma_tf32(acc[mt][nt], afr[mt], bfr[nt]);
        }
        __syncthreads();
    }

    // epilogue: per (mt,nt): pairs (c0,c1)@(m, n..n+1), (c2,c3)@(m+8, n..n+1)
    #pragma unroll
    for (int mt = 0; mt < 4; ++mt) {
        #pragma unroll
        for (int nt = 0; nt < 4; ++nt) {
            const int m = m0 + wm + mt*16 + g;
            const int n = n0 + wn + nt*8 + 2*c;
            float v0 = acc[mt][nt][0], v1 = acc[mt][nt][1];
            float v2 = acc[mt][nt][2], v3 = acc[mt][nt][3];
            if (EPI == 1) {
                float b0 = bias[n], b1 = bias[n+1];
                float t0 = v0 + b0; v0 = (t0 > 20.f) ? t0 : log1pf(__expf(t0));
                float t1 = v1 + b1; v1 = (t1 > 20.f) ? t1 : log1pf(__expf(t1));
                float t2 = v2 + b0; v2 = (t2 > 20.f) ? t2 : log1pf(__expf(t2));
                float t3 = v3 + b1; v3 = (t3 > 20.f) ? t3 : log1pf(__expf(t3));
            } else if (EPI == 2) {
                const float2 r0 = *reinterpret_cast<const float2*>(resid + (size_t)m*N + n);
                const float2 r1 = *reinterpret_cast<const float2*>(resid + (size_t)(m+8)*N + n);
                v0 += r0.x; v1 += r0.y; v2 += r1.x; v3 += r1.y;
            }
            *reinterpret_cast<float2*>(C + (size_t)m*N + n)     = make_float2(v0, v1);
            *reinterpret_cast<float2*>(C + (size_t)(m+8)*N + n) = make_float2(v2, v3);
        }
    }
}

// ---------------- RMSNorm ----------------
__global__ __launch_bounds__(256) void rmsnorm_kernel(
    const float* __restrict__ x, const float* __restrict__ w, float* __restrict__ xn)
{
    __shared__ float red[8];
    __shared__ float s_scale;
    int m = blockIdx.x, tid = threadIdx.x;
    float4 v = reinterpret_cast<const float4*>(x + (size_t)m*DMODEL)[tid];
    float s = v.x*v.x + v.y*v.y + v.z*v.z + v.w*v.w;
    #pragma unroll
    for (int o = 16; o > 0; o >>= 1) s += __shfl_xor_sync(0xffffffffu, s, o);
    if ((tid & 31) == 0) red[tid >> 5] = s;
    __syncthreads();
    if (tid < 32) {
        float t = (tid < 8) ? red[tid] : 0.f;
        #pragma unroll
        for (int o = 4; o > 0; o >>= 1) t += __shfl_xor_sync(0xffffffffu, t, o);
        if (tid == 0) s_scale = rsqrtf(t * (1.0f/DMODEL) + 1e-6f);
    }
    __syncthreads();
    float sc = s_scale;
    float4 wv = reinterpret_cast<const float4*>(w)[tid];
    float4 o;
    o.x = v.x*sc*wv.x; o.y = v.y*sc*wv.y; o.z = v.z*sc*wv.z; o.w = v.w*sc*wv.w;
    reinterpret_cast<float4*>(xn + (size_t)m*DMODEL)[tid] = o;
}

// ---------------- Depthwise causal conv (k=4) + bias + SiLU ----------------
__global__ __launch_bounds__(256) void conv_silu_kernel(
    const float* __restrict__ xz, const float* __restrict__ cw,
    const float* __restrict__ cb, float* __restrict__ uc)
{
    int idx = blockIdx.x * 256 + threadIdx.x;
    int d = idx & (DINNER-1);
    int m = idx >> 11;
    int l = m & (LL-1);
    float4 wv = reinterpret_cast<const float4*>(cw)[d];
    const float* up = xz + (size_t)m * (2*DINNER) + d;
    float acc = cb[d];
    acc = fmaf(up[0], wv.w, acc);
    if (l >= 1) acc = fmaf(up[-1*(2*DINNER)], wv.z, acc);
    if (l >= 2) acc = fmaf(up[-2*(2*DINNER)], wv.y, acc);
    if (l >= 3) acc = fmaf(up[-3*(2*DINNER)], wv.x, acc);
    uc[idx] = acc / (1.f + __expf(-acc));
}

// ---------------- Selective scan ----------------
#define SCL 64
#define SWP 8
__global__ __launch_bounds__(256) void scan_kernel(
    const float* __restrict__ xz,  const float* __restrict__ uc,
    const float* __restrict__ dbl, const float* __restrict__ dt,
    const float* __restrict__ A_log, const float* __restrict__ D_param,
    float* __restrict__ y)
{
    __shared__ float sB [SCL][DSTATE];
    __shared__ float sC [SCL][DSTATE];
    __shared__ float sdt[SCL][SWP];
    __shared__ float su [SCL][SWP];
    __shared__ float sz [SCL][SWP];
    __shared__ float sy [SCL][SWP];

    const int b    = blockIdx.y;
    const int d0   = blockIdx.x * SWP;
    const int tid  = threadIdx.x;
    const int w    = tid >> 5;
    const int lane = tid & 31;
    const int d    = d0 + w;
    const int mb   = b * LL;

    const float Aln = -__expf(A_log[d*DSTATE + lane]);
    const float Dd  = D_param[d];
    float h = 0.f;

    for (int c0 = 0; c0 < LL; c0 += SCL) {
        for (int idx = tid; idx < SCL*DSTATE; idx += 256) {
            int t = idx >> 5, n = idx & 31;
            int m = mb + c0 + t;
            sB[t][n] = dbl[(size_t)m*XPROJ_N + DTRANK + n];
            sC[t][n] = dbl[(size_t)m*XPROJ_N + DTRANK + DSTATE + n];
        }
        for (int idx = tid; idx < SCL*SWP; idx += 256) {
            int t = idx >> 3, dd = idx & 7;
            int m = mb + c0 + t;
            sdt[t][dd] = dt[(size_t)m*DINNER + d0 + dd];
            su [t][dd] = uc[(size_t)m*DINNER + d0 + dd];
            sz [t][dd] = xz[(size_t)m*(2*DINNER) + DINNER + d0 + dd];
        }
        __syncthreads();

        #pragma unroll 4
        for (int t = 0; t < SCL; ++t) {
            float dtv = sdt[t][w];
            float uv  = su[t][w];
            float dA  = __expf(dtv * Aln);
            h = fmaf(dA, h, (dtv * uv) * sB[t][lane]);
            float p = h * sC[t][lane];
            p += __shfl_xor_sync(0xffffffffu, p, 16);
            p += __shfl_xor_sync(0xffffffffu, p, 8);
            p += __shfl_xor_sync(0xffffffffu, p, 4);
            p += __shfl_xor_sync(0xffffffffu, p, 2);
            p += __shfl_xor_sync(0xffffffffu, p, 1);
            if (lane == 0) {
                float yv = p + uv * Dd;
                float zv = sz[t][w];
                sy[t][w] = yv * (zv / (1.f + __expf(-zv)));
            }
        }
        __syncthreads();

        for (int idx = tid; idx < SCL*SWP; idx += 256) {
            int t = idx >> 3, dd = idx & 7;
            y[(size_t)(mb + c0 + t)*DINNER + d0 + dd] = sy[t][dd];
        }
    }
}

// ---------------- Launch ----------------
extern "C" void kernel_launch(void* const* d_in, const int* in_sizes, int n_in,
                              void* d_out, int out_size)
{
    const float* x         = (const float*)d_in[0];
    const float* norm_w    = (const float*)d_in[1];
    const float* in_proj_w = (const float*)d_in[2];
    const float* conv_w    = (const float*)d_in[3];
    const float* conv_b    = (const float*)d_in[4];
    const float* x_proj_w  = (const float*)d_in[5];
    const float* dt_proj_w = (const float*)d_in[6];
    const float* dt_proj_b = (const float*)d_in[7];
    const float* A_log     = (const float*)d_in[8];
    const float* D_param   = (const float*)d_in[9];
    const float* out_proj_w= (const float*)d_in[10];
    float* out = (float*)d_out;

    float *p_xn, *p_xz, *p_uc, *p_dbl, *p_dt, *p_y;
    cudaGetSymbolAddress((void**)&p_xn,  g_xn);
    cudaGetSymbolAddress((void**)&p_xz,  g_xz);
    cudaGetSymbolAddress((void**)&p_uc,  g_uc);
    cudaGetSymbolAddress((void**)&p_dbl, g_dbl);
    cudaGetSymbolAddress((void**)&p_dt,  g_dt);
    cudaGetSymbolAddress((void**)&p_y,   g_y);
    cudaFuncSetAttribute(mma_gemm<0>, cudaFuncAttributeMaxDynamicSharedMemorySize, SMEM_TOTAL);
    cudaFuncSetAttribute(mma_gemm<1>, cudaFuncAttributeMaxDynamicSharedMemorySize, SMEM_TOTAL);
    cudaFuncSetAttribute(mma_gemm<2>, cudaFuncAttributeMaxDynamicSharedMemorySize, SMEM_TOTAL);

    // 1) RMSNorm
    rmsnorm_kernel<<<MM, 256>>>(x, norm_w, p_xn);

    // 2) in_proj: xz[8192,4096] = xn @ in_proj_w^T
    mma_gemm<0><<<dim3((2*DINNER)/128, MM/128), 256, SMEM_TOTAL>>>(
        p_xn, DMODEL, in_proj_w, p_xz, 2*DINNER, DMODEL, nullptr, nullptr);

    // 3) conv + silu
    conv_silu_kernel<<<(MM*DINNER)/256, 256>>>(p_xz, conv_w, conv_b, p_uc);

    // 4) x_proj: dbl[8192,128] = uc @ x_proj_w^T
    mma_gemm<0><<<dim3(XPROJ_N/128, MM/128), 256, SMEM_TOTAL>>>(
        p_uc, DINNER, x_proj_w, p_dbl, XPROJ_N, DINNER, nullptr, nullptr);

    // 5) dt_proj + softplus (A = first 64 cols of dbl, lda=128)
    mma_gemm<1><<<dim3(DINNER/128, MM/128), 256, SMEM_TOTAL>>>(
        p_dbl, XPROJ_N, dt_proj_w, p_dt, DINNER, DTRANK, dt_proj_b, nullptr);

    // 6) selective scan + skip + gate
    scan_kernel<<<dim3(DINNER/SWP, BB), 256>>>(
        p_xz, p_uc, p_dbl, p_dt, A_log, D_param, p_y);

    // 7) out_proj + residual
    mma_gemm<2><<<dim3(DMODEL/128, MM/128), 256, SMEM_TOTAL>>>(
        p_y, DINNER, out_proj_w, out, DMODEL, DINNER, nullptr, x);
}

// round 8
// speedup vs baseline: 2.1416x; 1.0790x over previous
#include <cuda_runtime.h>
#include <cuda_bf16.h>
#include <math.h>
#include <stdint.h>

// ---------------- Problem constants ----------------
#define BB 4
#define LL 2048
#define DMODEL 1024
#define DINNER 2048
#define DSTATE 32
#define DTRANK 64
#define MM (BB*LL)          // 8192 rows
#define XPROJ_N 128

// ---------------- Scratch ----------------
__device__ float g_xn [MM*DMODEL];
__device__ float g_xz [MM*(2*DINNER)];
__device__ float g_uc [MM*DINNER];
__device__ float g_dbl[MM*XPROJ_N];
__device__ float g_dt [MM*DINNER];
__device__ float g_y  [MM*DINNER];

// ---------------- helpers ----------------
__device__ __forceinline__ uint32_t smem_u32(const void* p){
    uint32_t a;
    asm("{ .reg .u64 t; cvta.to.shared.u64 t, %1; cvt.u32.u64 %0, t; }" : "=r"(a) : "l"(p));
    return a;
}
__device__ __forceinline__ void mma_tf32(float* c, const uint32_t* a, const uint32_t* b){
    asm volatile(
        "mma.sync.aligned.m16n8k8.row.col.f32.tf32.tf32.f32 "
        "{%0,%1,%2,%3}, {%4,%5,%6,%7}, {%8,%9}, {%0,%1,%2,%3};"
        : "+f"(c[0]), "+f"(c[1]), "+f"(c[2]), "+f"(c[3])
        : "r"(a[0]), "r"(a[1]), "r"(a[2]), "r"(a[3]), "r"(b[0]), "r"(b[1]));
}
__device__ __forceinline__ void ldsm4(uint32_t* r, uint32_t addr){
    asm volatile("ldmatrix.sync.aligned.m8n8.x4.shared.b16 {%0,%1,%2,%3}, [%4];"
        : "=r"(r[0]), "=r"(r[1]), "=r"(r[2]), "=r"(r[3]) : "r"(addr));
}

// ---------------- tf32 mma.sync GEMM (ldmatrix fragments, raw-f32 tf32) -------
// C[m,n] = sum_k A[m,k]*Bw[n,k]; A row-major lda, Bw row-major [N,K].
// BM=32*MT (128 or 64), BN=128, BK=32. 256 threads = 8 warps (2 m x 4 n).
// Warp tile (16*MT) x 32. EPI: 0 none, 1 softplus(acc+bias[n]), 2 acc+resid.
#define GP 36                      // smem row pitch in floats
#define TILE_ROW_BYTES (GP*4)      // 144

template<int MT, int EPI>
__global__ __launch_bounds__(256, 2) void mma_gemm(
    const float* __restrict__ A, int lda,
    const float* __restrict__ Bw,
    float* __restrict__ C,
    int N, int K,
    const float* __restrict__ bias,
    const float* __restrict__ resid)
{
    constexpr int BM  = 32*MT;
    constexpr int SAB = BM * TILE_ROW_BYTES;        // A stage bytes
    constexpr int SBB = 128 * TILE_ROW_BYTES;       // B stage bytes
    constexpr int STG = SAB + SBB;                  // one stage (A then B)

    extern __shared__ char dynsmem[];
    const uint32_t sm32 = smem_u32(dynsmem);

    const int tid  = threadIdx.x;
    const int wid  = tid >> 5, lane = tid & 31;
    const int g    = lane >> 2;            // 0..7
    const int c2   = (lane & 3) * 2;       // epilogue n offset
    const int wm   = (wid >> 2) * (16*MT); // warp m offset
    const int wn   = (wid & 3) * 32;       // warp n offset
    const int m0   = blockIdx.y * BM;
    const int n0   = blockIdx.x * 128;

    // gmem->smem: row = tid/8 (+32*i), 16B chunk = tid%8
    const int lrow = tid >> 3;
    const int lk16 = (tid & 7) * 16;

    const float* Ap0 = A  + (size_t)(m0 + lrow) * lda + (lk16 >> 2);
    const float* Bp0 = Bw + (size_t)(n0 + lrow) * K   + (lk16 >> 2);

    // per-thread ldmatrix byte offsets within a stage
    const uint32_t aoff = ((wm + (lane & 15))*GP + (lane >> 4)*4) * 4;
    const uint32_t boff = ((wn + 8*(lane >> 4) + (lane & 7))*GP + ((lane >> 3) & 1)*4) * 4;

    float acc[MT][4][4];
    #pragma unroll
    for (int i = 0; i < MT; ++i)
        #pragma unroll
        for (int j = 0; j < 4; ++j)
            #pragma unroll
            for (int q = 0; q < 4; ++q) acc[i][j][q] = 0.f;

    const int KT = K / 32;

    // prologue: tile 0 -> stage 0
    {
        #pragma unroll
        for (int i = 0; i < MT; ++i)
            asm volatile("cp.async.cg.shared.global [%0], [%1], 16;"
                :: "r"(sm32 + (lrow + 32*i)*TILE_ROW_BYTES + lk16),
                   "l"(Ap0 + (size_t)(32*i)*lda));
        #pragma unroll
        for (int i = 0; i < 4; ++i)
            asm volatile("cp.async.cg.shared.global [%0], [%1], 16;"
                :: "r"(sm32 + SAB + (lrow + 32*i)*TILE_ROW_BYTES + lk16),
                   "l"(Bp0 + (size_t)(32*i)*K));
        asm volatile("cp.async.commit_group;" ::: "memory");
    }

    for (int kt = 0; kt < KT; ++kt) {
        const int s = kt & 1;
        if (kt + 1 < KT) {
            const uint32_t da = sm32 + (1 - s)*STG;
            const float* Apn = Ap0 + (kt + 1)*32;
            const float* Bpn = Bp0 + (kt + 1)*32;
            #pragma unroll
            for (int i = 0; i < MT; ++i)
                asm volatile("cp.async.cg.shared.global [%0], [%1], 16;"
                    :: "r"(da + (lrow + 32*i)*TILE_ROW_BYTES + lk16),
                       "l"(Apn + (size_t)(32*i)*lda));
            #pragma unroll
            for (int i = 0; i < 4; ++i)
                asm volatile("cp.async.cg.shared.global [%0], [%1], 16;"
                    :: "r"(da + SAB + (lrow + 32*i)*TILE_ROW_BYTES + lk16),
                       "l"(Bpn + (size_t)(32*i)*K));
            asm volatile("cp.async.commit_group;" ::: "memory");
            asm volatile("cp.async.wait_group 1;" ::: "memory");
        } else {
            asm volatile("cp.async.wait_group 0;" ::: "memory");
        }
        __syncthreads();

        const uint32_t sA = sm32 + s*STG;
        const uint32_t sB = sA + SAB;
        #pragma unroll
        for (int k8 = 0; k8 < 4; ++k8) {
            const uint32_t kbyte = k8 * 32;
            uint32_t afr[MT][4];
            #pragma unroll
            for (int mt = 0; mt < MT; ++mt)
                ldsm4(afr[mt], sA + aoff + mt*(16*TILE_ROW_BYTES) + kbyte);
            uint32_t bfr[4][2];
            {
                uint32_t t0[4], t1[4];
                ldsm4(t0, sB + boff + kbyte);                        // nt0, nt1
                ldsm4(t1, sB + boff + 16*TILE_ROW_BYTES + kbyte);    // nt2, nt3
                bfr[0][0]=t0[0]; bfr[0][1]=t0[1]; bfr[1][0]=t0[2]; bfr[1][1]=t0[3];
                bfr[2][0]=t1[0]; bfr[2][1]=t1[1]; bfr[3][0]=t1[2]; bfr[3][1]=t1[3];
            }
            #pragma unroll
            for (int mt = 0; mt < MT; ++mt)
                #pragma unroll
                for (int nt = 0; nt < 4; ++nt)
                    mma_tf32(acc[mt][nt], afr[mt], bfr[nt]);
        }
        __syncthreads();
    }

    // epilogue
    #pragma unroll
    for (int mt = 0; mt < MT; ++mt) {
        #pragma unroll
        for (int nt = 0; nt < 4; ++nt) {
            const int m = m0 + wm + mt*16 + g;
            const int n = n0 + wn + nt*8 + c2;
            float v0 = acc[mt][nt][0], v1 = acc[mt][nt][1];
            float v2 = acc[mt][nt][2], v3 = acc[mt][nt][3];
            if (EPI == 1) {
                float b0 = bias[n], b1 = bias[n+1];
                float t0 = v0 + b0; v0 = (t0 > 20.f) ? t0 : log1pf(__expf(t0));
                float t1 = v1 + b1; v1 = (t1 > 20.f) ? t1 : log1pf(__expf(t1));
                float t2 = v2 + b0; v2 = (t2 > 20.f) ? t2 : log1pf(__expf(t2));
                float t3 = v3 + b1; v3 = (t3 > 20.f) ? t3 : log1pf(__expf(t3));
            } else if (EPI == 2) {
                const float2 r0 = *reinterpret_cast<const float2*>(resid + (size_t)m*N + n);
                const float2 r1 = *reinterpret_cast<const float2*>(resid + (size_t)(m+8)*N + n);
                v0 += r0.x; v1 += r0.y; v2 += r1.x; v3 += r1.y;
            }
            *reinterpret_cast<float2*>(C + (size_t)m*N + n)     = make_float2(v0, v1);
            *reinterpret_cast<float2*>(C + (size_t)(m+8)*N + n) = make_float2(v2, v3);
        }
    }
}

#define SMEM_MT4 (2*((128*TILE_ROW_BYTES) + (128*TILE_ROW_BYTES)))  // 73728
#define SMEM_MT2 (2*(( 64*TILE_ROW_BYTES) + (128*TILE_ROW_BYTES)))  // 55296

// ---------------- RMSNorm ----------------
__global__ __launch_bounds__(256) void rmsnorm_kernel(
    const float* __restrict__ x, const float* __restrict__ w, float* __restrict__ xn)
{
    __shared__ float red[8];
    __shared__ float s_scale;
    int m = blockIdx.x, tid = threadIdx.x;
    float4 v = reinterpret_cast<const float4*>(x + (size_t)m*DMODEL)[tid];
    float s = v.x*v.x + v.y*v.y + v.z*v.z + v.w*v.w;
    #pragma unroll
    for (int o = 16; o > 0; o >>= 1) s += __shfl_xor_sync(0xffffffffu, s, o);
    if ((tid & 31) == 0) red[tid >> 5] = s;
    __syncthreads();
    if (tid < 32) {
        float t = (tid < 8) ? red[tid] : 0.f;
        #pragma unroll
        for (int o = 4; o > 0; o >>= 1) t += __shfl_xor_sync(0xffffffffu, t, o);
        if (tid == 0) s_scale = rsqrtf(t * (1.0f/DMODEL) + 1e-6f);
    }
    __syncthreads();
    float sc = s_scale;
    float4 wv = reinterpret_cast<const float4*>(w)[tid];
    float4 o;
    o.x = v.x*sc*wv.x; o.y = v.y*sc*wv.y; o.z = v.z*sc*wv.z; o.w = v.w*sc*wv.w;
    reinterpret_cast<float4*>(xn + (size_t)m*DMODEL)[tid] = o;
}

// ---------------- Depthwise causal conv (k=4) + bias + SiLU ----------------
__global__ __launch_bounds__(256) void conv_silu_kernel(
    const float* __restrict__ xz, const float* __restrict__ cw,
    const float* __restrict__ cb, float* __restrict__ uc)
{
    int idx = blockIdx.x * 256 + threadIdx.x;
    int d = idx & (DINNER-1);
    int m = idx >> 11;
    int l = m & (LL-1);
    float4 wv = reinterpret_cast<const float4*>(cw)[d];
    const float* up = xz + (size_t)m * (2*DINNER) + d;
    float acc = cb[d];
    acc = fmaf(up[0], wv.w, acc);
    if (l >= 1) acc = fmaf(up[-1*(2*DINNER)], wv.z, acc);
    if (l >= 2) acc = fmaf(up[-2*(2*DINNER)], wv.y, acc);
    if (l >= 3) acc = fmaf(up[-3*(2*DINNER)], wv.x, acc);
    uc[idx] = acc / (1.f + __expf(-acc));
}

// ---------------- Selective scan ----------------
#define SCL 64
#define SWP 8
__global__ __launch_bounds__(256) void scan_kernel(
    const float* __restrict__ xz,  const float* __restrict__ uc,
    const float* __restrict__ dbl, const float* __restrict__ dt,
    const float* __restrict__ A_log, const float* __restrict__ D_param,
    float* __restrict__ y)
{
    __shared__ float sB [SCL][DSTATE];
    __shared__ float sC [SCL][DSTATE];
    __shared__ float sdt[SCL][SWP];
    __shared__ float su [SCL][SWP];
    __shared__ float sz [SCL][SWP];
    __shared__ float sy [SCL][SWP];

    const int b    = blockIdx.y;
    const int d0   = blockIdx.x * SWP;
    const int tid  = threadIdx.x;
    const int w    = tid >> 5;
    const int lane = tid & 31;
    const int d    = d0 + w;
    const int mb   = b * LL;

    const float Aln = -__expf(A_log[d*DSTATE + lane]);
    const float Dd  = D_param[d];
    float h = 0.f;

    for (int c0 = 0; c0 < LL; c0 += SCL) {
        for (int idx = tid; idx < SCL*DSTATE; idx += 256) {
            int t = idx >> 5, n = idx & 31;
            int m = mb + c0 + t;
            sB[t][n] = dbl[(size_t)m*XPROJ_N + DTRANK + n];
            sC[t][n] = dbl[(size_t)m*XPROJ_N + DTRANK + DSTATE + n];
        }
        for (int idx = tid; idx < SCL*SWP; idx += 256) {
            int t = idx >> 3, dd = idx & 7;
            int m = mb + c0 + t;
            sdt[t][dd] = dt[(size_t)m*DINNER + d0 + dd];
            su [t][dd] = uc[(size_t)m*DINNER + d0 + dd];
            sz [t][dd] = xz[(size_t)m*(2*DINNER) + DINNER + d0 + dd];
        }
        __syncthreads();

        #pragma unroll 4
        for (int t = 0; t < SCL; ++t) {
            float dtv = sdt[t][w];
            float uv  = su[t][w];
            float dA  = __expf(dtv * Aln);
            h = fmaf(dA, h, (dtv * uv) * sB[t][lane]);
            float p = h * sC[t][lane];
            p += __shfl_xor_sync(0xffffffffu, p, 16);
            p += __shfl_xor_sync(0xffffffffu, p, 8);
            p += __shfl_xor_sync(0xffffffffu, p, 4);
            p += __shfl_xor_sync(0xffffffffu, p, 2);
            p += __shfl_xor_sync(0xffffffffu, p, 1);
            if (lane == 0) {
                float yv = p + uv * Dd;
                float zv = sz[t][w];
                sy[t][w] = yv * (zv / (1.f + __expf(-zv)));
            }
        }
        __syncthreads();

        for (int idx = tid; idx < SCL*SWP; idx += 256) {
            int t = idx >> 3, dd = idx & 7;
            y[(size_t)(mb + c0 + t)*DINNER + d0 + dd] = sy[t][dd];
        }
    }
}

// ---------------- Launch ----------------
extern "C" void kernel_launch(void* const* d_in, const int* in_sizes, int n_in,
                              void* d_out, int out_size)
{
    const float* x         = (const float*)d_in[0];
    const float* norm_w    = (const float*)d_in[1];
    const float* in_proj_w = (const float*)d_in[2];
    const float* conv_w    = (const float*)d_in[3];
    const float* conv_b    = (const float*)d_in[4];
    const float* x_proj_w  = (const float*)d_in[5];
    const float* dt_proj_w = (const float*)d_in[6];
    const float* dt_proj_b = (const float*)d_in[7];
    const float* A_log     = (const float*)d_in[8];
    const float* D_param   = (const float*)d_in[9];
    const float* out_proj_w= (const float*)d_in[10];
    float* out = (float*)d_out;

    float *p_xn, *p_xz, *p_uc, *p_dbl, *p_dt, *p_y;
    cudaGetSymbolAddress((void**)&p_xn,  g_xn);
    cudaGetSymbolAddress((void**)&p_xz,  g_xz);
    cudaGetSymbolAddress((void**)&p_uc,  g_uc);
    cudaGetSymbolAddress((void**)&p_dbl, g_dbl);
    cudaGetSymbolAddress((void**)&p_dt,  g_dt);
    cudaGetSymbolAddress((void**)&p_y,   g_y);
    cudaFuncSetAttribute(mma_gemm<4,0>, cudaFuncAttributeMaxDynamicSharedMemorySize, SMEM_MT4);
    cudaFuncSetAttribute(mma_gemm<2,0>, cudaFuncAttributeMaxDynamicSharedMemorySize, SMEM_MT2);
    cudaFuncSetAttribute(mma_gemm<4,1>, cudaFuncAttributeMaxDynamicSharedMemorySize, SMEM_MT4);
    cudaFuncSetAttribute(mma_gemm<4,2>, cudaFuncAttributeMaxDynamicSharedMemorySize, SMEM_MT4);

    // 1) RMSNorm
    rmsnorm_kernel<<<MM, 256>>>(x, norm_w, p_xn);

    // 2) in_proj: xz[8192,4096] = xn @ in_proj_w^T
    mma_gemm<4,0><<<dim3((2*DINNER)/128, MM/128), 256, SMEM_MT4>>>(
        p_xn, DMODEL, in_proj_w, p_xz, 2*DINNER, DMODEL, nullptr, nullptr);

    // 3) conv + silu
    conv_silu_kernel<<<(MM*DINNER)/256, 256>>>(p_xz, conv_w, conv_b, p_uc);

    // 4) x_proj: dbl[8192,128] = uc @ x_proj_w^T  (BM=64 to fill the chip)
    mma_gemm<2,0><<<dim3(XPROJ_N/128, MM/64), 256, SMEM_MT2>>>(
        p_uc, DINNER, x_proj_w, p_dbl, XPROJ_N, DINNER, nullptr, nullptr);

    // 5) dt_proj + softplus (A = first 64 cols of dbl, lda=128)
    mma_gemm<4,1><<<dim3(DINNER/128, MM/128), 256, SMEM_MT4>>>(
        p_dbl, XPROJ_N, dt_proj_w, p_dt, DINNER, DTRANK, dt_proj_b, nullptr);

    // 6) selective scan + skip + gate
    scan_kernel<<<dim3(DINNER/SWP, BB), 256>>>(
        p_xz, p_uc, p_dbl, p_dt, A_log, D_param, p_y);

    // 7) out_proj + residual
    mma_gemm<4,2><<<dim3(DMODEL/128, MM/128), 256, SMEM_MT4>>>(
        p_y, DINNER, out_proj_w, out, DMODEL, DINNER, nullptr, x);
}

// round 10
// speedup vs baseline: 2.1568x; 1.0071x over previous
#include <cuda_runtime.h>
#include <cuda_bf16.h>
#include <math.h>
#include <stdint.h>

// ---------------- Problem constants ----------------
#define BB 4
#define LL 2048
#define DMODEL 1024
#define DINNER 2048
#define DSTATE 32
#define DTRANK 64
#define MM (BB*LL)          // 8192 rows
#define XPROJ_N 128

// ---------------- Scratch ----------------
__device__ float g_xn [MM*DMODEL];
__device__ float g_xz [MM*(2*DINNER)];
__device__ float g_uc [MM*DINNER];
__device__ float g_dbl[MM*XPROJ_N];
__device__ float g_dt [MM*DINNER];
__device__ float g_y  [MM*DINNER];

// ---------------- helpers ----------------
__device__ __forceinline__ uint32_t smem_u32(const void* p){
    uint32_t a;
    asm("{ .reg .u64 t; cvta.to.shared.u64 t, %1; cvt.u32.u64 %0, t; }" : "=r"(a) : "l"(p));
    return a;
}
__device__ __forceinline__ void mma_tf32(float* c, const uint32_t* a, const uint32_t* b){
    asm volatile(
        "mma.sync.aligned.m16n8k8.row.col.f32.tf32.tf32.f32 "
        "{%0,%1,%2,%3}, {%4,%5,%6,%7}, {%8,%9}, {%0,%1,%2,%3};"
        : "+f"(c[0]), "+f"(c[1]), "+f"(c[2]), "+f"(c[3])
        : "r"(a[0]), "r"(a[1]), "r"(a[2]), "r"(a[3]), "r"(b[0]), "r"(b[1]));
}
__device__ __forceinline__ void ldsm4(uint32_t* r, uint32_t addr){
    asm volatile("ldmatrix.sync.aligned.m8n8.x4.shared.b16 {%0,%1,%2,%3}, [%4];"
        : "=r"(r[0]), "=r"(r[1]), "=r"(r[2]), "=r"(r[3]) : "r"(addr));
}

// ---------------- tf32 mma.sync GEMM (3-stage cp.async, ldmatrix) -------------
// C[m,n] = sum_k A[m,k]*Bw[n,k]; A row-major lda, Bw row-major [N,K].
// BM=32*MT (128 or 64), BN=128, BK=32. 256 threads = 8 warps (2 m x 4 n).
// EPI: 0 none, 1 softplus(acc+bias[n]), 2 acc+resid.
#define GP 36                      // smem row pitch in floats
#define TILE_ROW_BYTES (GP*4)      // 144

template<int MT, int EPI>
__global__ __launch_bounds__(256, 2) void mma_gemm(
    const float* __restrict__ A, int lda,
    const float* __restrict__ Bw,
    float* __restrict__ C,
    int N, int K,
    const float* __restrict__ bias,
    const float* __restrict__ resid)
{
    constexpr int BM  = 32*MT;
    constexpr int SAB = BM * TILE_ROW_BYTES;        // A stage bytes
    constexpr int SBB = 128 * TILE_ROW_BYTES;       // B stage bytes
    constexpr int STG = SAB + SBB;                  // one stage (A then B)

    extern __shared__ char dynsmem[];
    const uint32_t sm32 = smem_u32(dynsmem);

    const int tid  = threadIdx.x;
    const int wid  = tid >> 5, lane = tid & 31;
    const int g    = lane >> 2;
    const int c2   = (lane & 3) * 2;
    const int wm   = (wid >> 2) * (16*MT);
    const int wn   = (wid & 3) * 32;
    const int m0   = blockIdx.y * BM;
    const int n0   = blockIdx.x * 128;

    const int lrow = tid >> 3;
    const int lk16 = (tid & 7) * 16;

    const float* Ap0 = A  + (size_t)(m0 + lrow) * lda + (lk16 >> 2);
    const float* Bp0 = Bw + (size_t)(n0 + lrow) * K   + (lk16 >> 2);

    const uint32_t aoff = ((wm + (lane & 15))*GP + (lane >> 4)*4) * 4;
    const uint32_t boff = ((wn + 8*(lane >> 4) + (lane & 7))*GP + ((lane >> 3) & 1)*4) * 4;

    float acc[MT][4][4];
    #pragma unroll
    for (int i = 0; i < MT; ++i)
        #pragma unroll
        for (int j = 0; j < 4; ++j)
            #pragma unroll
            for (int q = 0; q < 4; ++q) acc[i][j][q] = 0.f;

    const int KT = K / 32;

    // prologue: tiles 0 and 1 -> stages 0 and 1 (separate commit groups)
    #pragma unroll
    for (int p = 0; p < 2; ++p) {
        if (p < KT) {
            const uint32_t da = sm32 + p*STG;
            const float* Apn = Ap0 + p*32;
            const float* Bpn = Bp0 + p*32;
            #pragma unroll
            for (int i = 0; i < MT; ++i)
                asm volatile("cp.async.cg.shared.global [%0], [%1], 16;"
                    :: "r"(da + (lrow + 32*i)*TILE_ROW_BYTES + lk16),
                       "l"(Apn + (size_t)(32*i)*lda));
            #pragma unroll
            for (int i = 0; i < 4; ++i)
                asm volatile("cp.async.cg.shared.global [%0], [%1], 16;"
                    :: "r"(da + SAB + (lrow + 32*i)*TILE_ROW_BYTES + lk16),
                       "l"(Bpn + (size_t)(32*i)*K));
            asm volatile("cp.async.commit_group;" ::: "memory");
        }
    }

    int s = 0, sp = 2;   // current compute stage, prefetch stage
    for (int kt = 0; kt < KT; ++kt) {
        if (kt + 2 < KT) {
            const uint32_t da = sm32 + sp*STG;
            const float* Apn = Ap0 + (kt + 2)*32;
            const float* Bpn = Bp0 + (kt + 2)*32;
            #pragma unroll
            for (int i = 0; i < MT; ++i)
                asm volatile("cp.async.cg.shared.global [%0], [%1], 16;"
                    :: "r"(da + (lrow + 32*i)*TILE_ROW_BYTES + lk16),
                       "l"(Apn + (size_t)(32*i)*lda));
            #pragma unroll
            for (int i = 0; i < 4; ++i)
                asm volatile("cp.async.cg.shared.global [%0], [%1], 16;"
                    :: "r"(da + SAB + (lrow + 32*i)*TILE_ROW_BYTES + lk16),
                       "l"(Bpn + (size_t)(32*i)*K));
            asm volatile("cp.async.commit_group;" ::: "memory");
            asm volatile("cp.async.wait_group 2;" ::: "memory");
        } else if (kt + 1 < KT) {
            asm volatile("cp.async.wait_group 1;" ::: "memory");
        } else {
            asm volatile("cp.async.wait_group 0;" ::: "memory");
        }
        __syncthreads();

        const uint32_t sA = sm32 + s*STG;
        const uint32_t sB = sA + SAB;
        #pragma unroll
        for (int k8 = 0; k8 < 4; ++k8) {
            const uint32_t kbyte = k8 * 32;
            uint32_t afr[MT][4];
            #pragma unroll
            for (int mt = 0; mt < MT; ++mt)
                ldsm4(afr[mt], sA + aoff + mt*(16*TILE_ROW_BYTES) + kbyte);
            uint32_t bfr[4][2];
            {
                uint32_t t0[4], t1[4];
                ldsm4(t0, sB + boff + kbyte);
                ldsm4(t1, sB + boff + 16*TILE_ROW_BYTES + kbyte);
                bfr[0][0]=t0[0]; bfr[0][1]=t0[1]; bfr[1][0]=t0[2]; bfr[1][1]=t0[3];
                bfr[2][0]=t1[0]; bfr[2][1]=t1[1]; bfr[3][0]=t1[2]; bfr[3][1]=t1[3];
            }
            #pragma unroll
            for (int mt = 0; mt < MT; ++mt)
                #pragma unroll
                for (int nt = 0; nt < 4; ++nt)
                    mma_tf32(acc[mt][nt], afr[mt], bfr[nt]);
        }
        __syncthreads();

        s  = (s  == 2) ? 0 : s + 1;
        sp = (sp == 2) ? 0 : sp + 1;
    }

    // epilogue
    #pragma unroll
    for (int mt = 0; mt < MT; ++mt) {
        #pragma unroll
        for (int nt = 0; nt < 4; ++nt) {
            const int m = m0 + wm + mt*16 + g;
            const int n = n0 + wn + nt*8 + c2;
            float v0 = acc[mt][nt][0], v1 = acc[mt][nt][1];
            float v2 = acc[mt][nt][2], v3 = acc[mt][nt][3];
            if (EPI == 1) {
                float b0 = bias[n], b1 = bias[n+1];
                float t0 = v0 + b0; v0 = (t0 > 20.f) ? t0 : __logf(1.f + __expf(t0));
                float t1 = v1 + b1; v1 = (t1 > 20.f) ? t1 : __logf(1.f + __expf(t1));
                float t2 = v2 + b0; v2 = (t2 > 20.f) ? t2 : __logf(1.f + __expf(t2));
                float t3 = v3 + b1; v3 = (t3 > 20.f) ? t3 : __logf(1.f + __expf(t3));
            } else if (EPI == 2) {
                const float2 r0 = *reinterpret_cast<const float2*>(resid + (size_t)m*N + n);
                const float2 r1 = *reinterpret_cast<const float2*>(resid + (size_t)(m+8)*N + n);
                v0 += r0.x; v1 += r0.y; v2 += r1.x; v3 += r1.y;
            }
            *reinterpret_cast<float2*>(C + (size_t)m*N + n)     = make_float2(v0, v1);
            *reinterpret_cast<float2*>(C + (size_t)(m+8)*N + n) = make_float2(v2, v3);
        }
    }
}

#define SMEM_MT4 (3*((128*TILE_ROW_BYTES) + (128*TILE_ROW_BYTES)))  // 110592
#define SMEM_MT2 (3*(( 64*TILE_ROW_BYTES) + (128*TILE_ROW_BYTES)))  // 82944

// ---------------- RMSNorm ----------------
__global__ __launch_bounds__(256) void rmsnorm_kernel(
    const float* __restrict__ x, const float* __restrict__ w, float* __restrict__ xn)
{
    __shared__ float red[8];
    __shared__ float s_scale;
    int m = blockIdx.x, tid = threadIdx.x;
    float4 v = reinterpret_cast<const float4*>(x + (size_t)m*DMODEL)[tid];
    float s = v.x*v.x + v.y*v.y + v.z*v.z + v.w*v.w;
    #pragma unroll
    for (int o = 16; o > 0; o >>= 1) s += __shfl_xor_sync(0xffffffffu, s, o);
    if ((tid & 31) == 0) red[tid >> 5] = s;
    __syncthreads();
    if (tid < 32) {
        float t = (tid < 8) ? red[tid] : 0.f;
        #pragma unroll
        for (int o = 4; o > 0; o >>= 1) t += __shfl_xor_sync(0xffffffffu, t, o);
        if (tid == 0) s_scale = rsqrtf(t * (1.0f/DMODEL) + 1e-6f);
    }
    __syncthreads();
    float sc = s_scale;
    float4 wv = reinterpret_cast<const float4*>(w)[tid];
    float4 o;
    o.x = v.x*sc*wv.x; o.y = v.y*sc*wv.y; o.z = v.z*sc*wv.z; o.w = v.w*sc*wv.w;
    reinterpret_cast<float4*>(xn + (size_t)m*DMODEL)[tid] = o;
}

// ---------------- Depthwise causal conv (k=4) + bias + SiLU ----------------
__global__ __launch_bounds__(256) void conv_silu_kernel(
    const float* __restrict__ xz, const float* __restrict__ cw,
    const float* __restrict__ cb, float* __restrict__ uc)
{
    int idx = blockIdx.x * 256 + threadIdx.x;
    int d = idx & (DINNER-1);
    int m = idx >> 11;
    int l = m & (LL-1);
    float4 wv = reinterpret_cast<const float4*>(cw)[d];
    const float* up = xz + (size_t)m * (2*DINNER) + d;
    float acc = cb[d];
    acc = fmaf(up[0], wv.w, acc);
    if (l >= 1) acc = fmaf(up[-1*(2*DINNER)], wv.z, acc);
    if (l >= 2) acc = fmaf(up[-2*(2*DINNER)], wv.y, acc);
    if (l >= 3) acc = fmaf(up[-3*(2*DINNER)], wv.x, acc);
    uc[idx] = acc / (1.f + __expf(-acc));
}

// ---------------- Selective scan ----------------
#define SCL 64
#define SWP 8
__global__ __launch_bounds__(256) void scan_kernel(
    const float* __restrict__ xz,  const float* __restrict__ uc,
    const float* __restrict__ dbl, const float* __restrict__ dt,
    const float* __restrict__ A_log, const float* __restrict__ D_param,
    float* __restrict__ y)
{
    __shared__ float sB [SCL][DSTATE];
    __shared__ float sC [SCL][DSTATE];
    __shared__ float sdt[SCL][SWP];
    __shared__ float su [SCL][SWP];
    __shared__ float sz [SCL][SWP];
    __shared__ float sy [SCL][SWP];

    const int b    = blockIdx.y;
    const int d0   = blockIdx.x * SWP;
    const int tid  = threadIdx.x;
    const int w    = tid >> 5;
    const int lane = tid & 31;
    const int d    = d0 + w;
    const int mb   = b * LL;

    const float Aln = -__expf(A_log[d*DSTATE + lane]);
    const float Dd  = D_param[d];
    float h = 0.f;

    for (int c0 = 0; c0 < LL; c0 += SCL) {
        for (int idx = tid; idx < SCL*DSTATE; idx += 256) {
            int t = idx >> 5, n = idx & 31;
            int m = mb + c0 + t;
            sB[t][n] = dbl[(size_t)m*XPROJ_N + DTRANK + n];
            sC[t][n] = dbl[(size_t)m*XPROJ_N + DTRANK + DSTATE + n];
        }
        for (int idx = tid; idx < SCL*SWP; idx += 256) {
            int t = idx >> 3, dd = idx & 7;
            int m = mb + c0 + t;
            sdt[t][dd] = dt[(size_t)m*DINNER + d0 + dd];
            su [t][dd] = uc[(size_t)m*DINNER + d0 + dd];
            sz [t][dd] = xz[(size_t)m*(2*DINNER) + DINNER + d0 + dd];
        }
        __syncthreads();

        #pragma unroll 4
        for (int t = 0; t < SCL; ++t) {
            float dtv = sdt[t][w];
            float uv  = su[t][w];
            float dA  = __expf(dtv * Aln);
            h = fmaf(dA, h, (dtv * uv) * sB[t][lane]);
            float p = h * sC[t][lane];
            p += __shfl_xor_sync(0xffffffffu, p, 16);
            p += __shfl_xor_sync(0xffffffffu, p, 8);
            p += __shfl_xor_sync(0xffffffffu, p, 4);
            p += __shfl_xor_sync(0xffffffffu, p, 2);
            p += __shfl_xor_sync(0xffffffffu, p, 1);
            if (lane == 0) {
                float yv = p + uv * Dd;
                float zv = sz[t][w];
                sy[t][w] = yv * (zv / (1.f + __expf(-zv)));
            }
        }
        __syncthreads();

        for (int idx = tid; idx < SCL*SWP; idx += 256) {
            int t = idx >> 3, dd = idx & 7;
            y[(size_t)(mb + c0 + t)*DINNER + d0 + dd] = sy[t][dd];
        }
    }
}

// ---------------- Launch ----------------
extern "C" void kernel_launch(void* const* d_in, const int* in_sizes, int n_in,
                              void* d_out, int out_size)
{
    const float* x         = (const float*)d_in[0];
    const float* norm_w    = (const float*)d_in[1];
    const float* in_proj_w = (const float*)d_in[2];
    const float* conv_w    = (const float*)d_in[3];
    const float* conv_b    = (const float*)d_in[4];
    const float* x_proj_w  = (const float*)d_in[5];
    const float* dt_proj_w = (const float*)d_in[6];
    const float* dt_proj_b = (const float*)d_in[7];
    const float* A_log     = (const float*)d_in[8];
    const float* D_param   = (const float*)d_in[9];
    const float* out_proj_w= (const float*)d_in[10];
    float* out = (float*)d_out;

    float *p_xn, *p_xz, *p_uc, *p_dbl, *p_dt, *p_y;
    cudaGetSymbolAddress((void**)&p_xn,  g_xn);
    cudaGetSymbolAddress((void**)&p_xz,  g_xz);
    cudaGetSymbolAddress((void**)&p_uc,  g_uc);
    cudaGetSymbolAddress((void**)&p_dbl, g_dbl);
    cudaGetSymbolAddress((void**)&p_dt,  g_dt);
    cudaGetSymbolAddress((void**)&p_y,   g_y);
    cudaFuncSetAttribute(mma_gemm<4,0>, cudaFuncAttributeMaxDynamicSharedMemorySize, SMEM_MT4);
    cudaFuncSetAttribute(mma_gemm<2,0>, cudaFuncAttributeMaxDynamicSharedMemorySize, SMEM_MT2);
    cudaFuncSetAttribute(mma_gemm<4,1>, cudaFuncAttributeMaxDynamicSharedMemorySize, SMEM_MT4);
    cudaFuncSetAttribute(mma_gemm<4,2>, cudaFuncAttributeMaxDynamicSharedMemorySize, SMEM_MT4);

    // 1) RMSNorm
    rmsnorm_kernel<<<MM, 256>>>(x, norm_w, p_xn);

    // 2) in_proj: xz[8192,4096] = xn @ in_proj_w^T
    mma_gemm<4,0><<<dim3((2*DINNER)/128, MM/128), 256, SMEM_MT4>>>(
        p_xn, DMODEL, in_proj_w, p_xz, 2*DINNER, DMODEL, nullptr, nullptr);

    // 3) conv + silu
    conv_silu_kernel<<<(MM*DINNER)/256, 256>>>(p_xz, conv_w, conv_b, p_uc);

    // 4) x_proj: dbl[8192,128] = uc @ x_proj_w^T  (BM=64 fills the chip)
    mma_gemm<2,0><<<dim3(XPROJ_N/128, MM/64), 256, SMEM_MT2>>>(
        p_uc, DINNER, x_proj_w, p_dbl, XPROJ_N, DINNER, nullptr, nullptr);

    // 5) dt_proj + softplus (A = first 64 cols of dbl, lda=128)
    mma_gemm<4,1><<<dim3(DINNER/128, MM/128), 256, SMEM_MT4>>>(
        p_dbl, XPROJ_N, dt_proj_w, p_dt, DINNER, DTRANK, dt_proj_b, nullptr);

    // 6) selective scan + skip + gate
    scan_kernel<<<dim3(DINNER/SWP, BB), 256>>>(
        p_xz, p_uc, p_dbl, p_dt, A_log, D_param, p_y);

    // 7) out_proj + residual
    mma_gemm<4,2><<<dim3(DMODEL/128, MM/128), 256, SMEM_MT4>>>(
        p_y, DINNER, out_proj_w, out, DMODEL, DINNER, nullptr, x);
}

// round 11
// speedup vs baseline: 2.1587x; 1.0009x over previous
#include <cuda_runtime.h>
#include <cuda_bf16.h>
#include <math.h>
#include <stdint.h>

// ---------------- Problem constants ----------------
#define BB 4
#define LL 2048
#define DMODEL 1024
#define DINNER 2048
#define DSTATE 32
#define DTRANK 64
#define MM (BB*LL)          // 8192 rows
#define XPROJ_N 128

// ---------------- Scratch ----------------
__device__ float g_xn [MM*DMODEL];
__device__ float g_xz [MM*(2*DINNER)];
__device__ float g_uc [MM*DINNER];
__device__ float g_dbl[MM*XPROJ_N];
__device__ float g_dt [MM*DINNER];
__device__ float g_y  [MM*DINNER];

// ---------------- helpers ----------------
__device__ __forceinline__ uint32_t smem_u32(const void* p){
    uint32_t a;
    asm("{ .reg .u64 t; cvta.to.shared.u64 t, %1; cvt.u32.u64 %0, t; }" : "=r"(a) : "l"(p));
    return a;
}
__device__ __forceinline__ void mma_tf32(float* c, const uint32_t* a, const uint32_t* b){
    asm volatile(
        "mma.sync.aligned.m16n8k8.row.col.f32.tf32.tf32.f32 "
        "{%0,%1,%2,%3}, {%4,%5,%6,%7}, {%8,%9}, {%0,%1,%2,%3};"
        : "+f"(c[0]), "+f"(c[1]), "+f"(c[2]), "+f"(c[3])
        : "r"(a[0]), "r"(a[1]), "r"(a[2]), "r"(a[3]), "r"(b[0]), "r"(b[1]));
}
__device__ __forceinline__ void ldsm4(uint32_t* r, uint32_t addr){
    asm volatile("ldmatrix.sync.aligned.m8n8.x4.shared.b16 {%0,%1,%2,%3}, [%4];"
        : "=r"(r[0]), "=r"(r[1]), "=r"(r[2]), "=r"(r[3]) : "r"(addr));
}

// ---------------- tf32 mma.sync GEMM (3-stage, 1 barrier/ktile, prefetch-first)
// C[m,n] = sum_k A[m,k]*Bw[n,k]; A row-major lda, Bw row-major [N,K].
// BM=32*MT (128/64/32), BN=128, BK=32. 256 threads = 8 warps (2 m x 4 n).
// EPI: 0 none, 1 softplus(acc+bias[n]), 2 acc+resid.
#define GP 36                      // smem row pitch in floats
#define TILE_ROW_BYTES (GP*4)      // 144

template<int MT, int EPI>
__global__ __launch_bounds__(256, 2) void mma_gemm(
    const float* __restrict__ A, int lda,
    const float* __restrict__ Bw,
    float* __restrict__ C,
    int N, int K,
    const float* __restrict__ bias,
    const float* __restrict__ resid)
{
    constexpr int BM  = 32*MT;
    constexpr int SAB = BM * TILE_ROW_BYTES;        // A stage bytes
    constexpr int SBB = 128 * TILE_ROW_BYTES;       // B stage bytes
    constexpr int STG = SAB + SBB;                  // one stage (A then B)

    extern __shared__ char dynsmem[];
    const uint32_t sm32 = smem_u32(dynsmem);

    const int tid  = threadIdx.x;
    const int wid  = tid >> 5, lane = tid & 31;
    const int g    = lane >> 2;
    const int c2   = (lane & 3) * 2;
    const int wm   = (wid >> 2) * (16*MT);
    const int wn   = (wid & 3) * 32;
    const int m0   = blockIdx.y * BM;
    const int n0   = blockIdx.x * 128;

    const int lrow = tid >> 3;
    const int lk16 = (tid & 7) * 16;

    const float* Ap0 = A  + (size_t)(m0 + lrow) * lda + (lk16 >> 2);
    const float* Bp0 = Bw + (size_t)(n0 + lrow) * K   + (lk16 >> 2);

    const uint32_t aoff = ((wm + (lane & 15))*GP + (lane >> 4)*4) * 4;
    const uint32_t boff = ((wn + 8*(lane >> 4) + (lane & 7))*GP + ((lane >> 3) & 1)*4) * 4;

    float acc[MT][4][4];
    #pragma unroll
    for (int i = 0; i < MT; ++i)
        #pragma unroll
        for (int j = 0; j < 4; ++j)
            #pragma unroll
            for (int q = 0; q < 4; ++q) acc[i][j][q] = 0.f;

    const int KT = K / 32;

    // prologue: tiles 0 and 1 -> stages 0 and 1 (separate commit groups)
    #pragma unroll
    for (int p = 0; p < 2; ++p) {
        if (p < KT) {
            const uint32_t da = sm32 + p*STG;
            const float* Apn = Ap0 + p*32;
            const float* Bpn = Bp0 + p*32;
            #pragma unroll
            for (int i = 0; i < MT; ++i)
                asm volatile("cp.async.cg.shared.global [%0], [%1], 16;"
                    :: "r"(da + (lrow + 32*i)*TILE_ROW_BYTES + lk16),
                       "l"(Apn + (size_t)(32*i)*lda));
            #pragma unroll
            for (int i = 0; i < 4; ++i)
                asm volatile("cp.async.cg.shared.global [%0], [%1], 16;"
                    :: "r"(da + SAB + (lrow + 32*i)*TILE_ROW_BYTES + lk16),
                       "l"(Bpn + (size_t)(32*i)*K));
            asm volatile("cp.async.commit_group;" ::: "memory");
        }
    }

    int s = 0, sp = 2;   // compute stage, prefetch stage
    for (int kt = 0; kt < KT; ++kt) {
        // data for tile kt ready (pending set is {kt, kt+1} at most)
        if (kt + 1 < KT) asm volatile("cp.async.wait_group 1;" ::: "memory");
        else             asm volatile("cp.async.wait_group 0;" ::: "memory");
        __syncthreads();   // collective visibility of tile kt; fences reads of stage sp from kt-1

        // prefetch tile kt+2 into stage sp BEFORE compute (overlaps with MMAs)
        if (kt + 2 < KT) {
            const uint32_t da = sm32 + sp*STG;
            const float* Apn = Ap0 + (kt + 2)*32;
            const float* Bpn = Bp0 + (kt + 2)*32;
            #pragma unroll
            for (int i = 0; i < MT; ++i)
                asm volatile("cp.async.cg.shared.global [%0], [%1], 16;"
                    :: "r"(da + (lrow + 32*i)*TILE_ROW_BYTES + lk16),
                       "l"(Apn + (size_t)(32*i)*lda));
            #pragma unroll
            for (int i = 0; i < 4; ++i)
                asm volatile("cp.async.cg.shared.global [%0], [%1], 16;"
                    :: "r"(da + SAB + (lrow + 32*i)*TILE_ROW_BYTES + lk16),
                       "l"(Bpn + (size_t)(32*i)*K));
            asm volatile("cp.async.commit_group;" ::: "memory");
        }

        // compute from stage s
        const uint32_t sA = sm32 + s*STG;
        const uint32_t sB = sA + SAB;
        #pragma unroll
        for (int k8 = 0; k8 < 4; ++k8) {
            const uint32_t kbyte = k8 * 32;
            uint32_t afr[MT][4];
            #pragma unroll
            for (int mt = 0; mt < MT; ++mt)
                ldsm4(afr[mt], sA + aoff + mt*(16*TILE_ROW_BYTES) + kbyte);
            uint32_t bfr[4][2];
            {
                uint32_t t0[4], t1[4];
                ldsm4(t0, sB + boff + kbyte);
                ldsm4(t1, sB + boff + 16*TILE_ROW_BYTES + kbyte);
                bfr[0][0]=t0[0]; bfr[0][1]=t0[1]; bfr[1][0]=t0[2]; bfr[1][1]=t0[3];
                bfr[2][0]=t1[0]; bfr[2][1]=t1[1]; bfr[3][0]=t1[2]; bfr[3][1]=t1[3];
            }
            #pragma unroll
            for (int mt = 0; mt < MT; ++mt)
                #pragma unroll
                for (int nt = 0; nt < 4; ++nt)
                    mma_tf32(acc[mt][nt], afr[mt], bfr[nt]);
        }

        s  = (s  == 2) ? 0 : s + 1;
        sp = (sp == 2) ? 0 : sp + 1;
    }

    // epilogue
    #pragma unroll
    for (int mt = 0; mt < MT; ++mt) {
        #pragma unroll
        for (int nt = 0; nt < 4; ++nt) {
            const int m = m0 + wm + mt*16 + g;
            const int n = n0 + wn + nt*8 + c2;
            float v0 = acc[mt][nt][0], v1 = acc[mt][nt][1];
            float v2 = acc[mt][nt][2], v3 = acc[mt][nt][3];
            if (EPI == 1) {
                float b0 = bias[n], b1 = bias[n+1];
                float t0 = v0 + b0; v0 = (t0 > 20.f) ? t0 : __logf(1.f + __expf(t0));
                float t1 = v1 + b1; v1 = (t1 > 20.f) ? t1 : __logf(1.f + __expf(t1));
                float t2 = v2 + b0; v2 = (t2 > 20.f) ? t2 : __logf(1.f + __expf(t2));
                float t3 = v3 + b1; v3 = (t3 > 20.f) ? t3 : __logf(1.f + __expf(t3));
            } else if (EPI == 2) {
                const float2 r0 = *reinterpret_cast<const float2*>(resid + (size_t)m*N + n);
                const float2 r1 = *reinterpret_cast<const float2*>(resid + (size_t)(m+8)*N + n);
                v0 += r0.x; v1 += r0.y; v2 += r1.x; v3 += r1.y;
            }
            *reinterpret_cast<float2*>(C + (size_t)m*N + n)     = make_float2(v0, v1);
            *reinterpret_cast<float2*>(C + (size_t)(m+8)*N + n) = make_float2(v2, v3);
        }
    }
}

#define SMEM_MT4 (3*((128*TILE_ROW_BYTES) + (128*TILE_ROW_BYTES)))  // 110592
#define SMEM_MT1 (3*(( 32*TILE_ROW_BYTES) + (128*TILE_ROW_BYTES)))  // 69120

// ---------------- RMSNorm ----------------
__global__ __launch_bounds__(256) void rmsnorm_kernel(
    const float* __restrict__ x, const float* __restrict__ w, float* __restrict__ xn)
{
    __shared__ float red[8];
    __shared__ float s_scale;
    int m = blockIdx.x, tid = threadIdx.x;
    float4 v = reinterpret_cast<const float4*>(x + (size_t)m*DMODEL)[tid];
    float s = v.x*v.x + v.y*v.y + v.z*v.z + v.w*v.w;
    #pragma unroll
    for (int o = 16; o > 0; o >>= 1) s += __shfl_xor_sync(0xffffffffu, s, o);
    if ((tid & 31) == 0) red[tid >> 5] = s;
    __syncthreads();
    if (tid < 32) {
        float t = (tid < 8) ? red[tid] : 0.f;
        #pragma unroll
        for (int o = 4; o > 0; o >>= 1) t += __shfl_xor_sync(0xffffffffu, t, o);
        if (tid == 0) s_scale = rsqrtf(t * (1.0f/DMODEL) + 1e-6f);
    }
    __syncthreads();
    float sc = s_scale;
    float4 wv = reinterpret_cast<const float4*>(w)[tid];
    float4 o;
    o.x = v.x*sc*wv.x; o.y = v.y*sc*wv.y; o.z = v.z*sc*wv.z; o.w = v.w*sc*wv.w;
    reinterpret_cast<float4*>(xn + (size_t)m*DMODEL)[tid] = o;
}

// ---------------- Depthwise causal conv (k=4) + bias + SiLU ----------------
__global__ __launch_bounds__(256) void conv_silu_kernel(
    const float* __restrict__ xz, const float* __restrict__ cw,
    const float* __restrict__ cb, float* __restrict__ uc)
{
    int idx = blockIdx.x * 256 + threadIdx.x;
    int d = idx & (DINNER-1);
    int m = idx >> 11;
    int l = m & (LL-1);
    float4 wv = reinterpret_cast<const float4*>(cw)[d];
    const float* up = xz + (size_t)m * (2*DINNER) + d;
    float acc = cb[d];
    acc = fmaf(up[0], wv.w, acc);
    if (l >= 1) acc = fmaf(up[-1*(2*DINNER)], wv.z, acc);
    if (l >= 2) acc = fmaf(up[-2*(2*DINNER)], wv.y, acc);
    if (l >= 3) acc = fmaf(up[-3*(2*DINNER)], wv.x, acc);
    uc[idx] = acc / (1.f + __expf(-acc));
}

// ---------------- Selective scan ----------------
#define SCL 64
#define SWP 8
__global__ __launch_bounds__(256) void scan_kernel(
    const float* __restrict__ xz,  const float* __restrict__ uc,
    const float* __restrict__ dbl, const float* __restrict__ dt,
    const float* __restrict__ A_log, const float* __restrict__ D_param,
    float* __restrict__ y)
{
    __shared__ float sB [SCL][DSTATE];
    __shared__ float sC [SCL][DSTATE];
    __shared__ float sdt[SCL][SWP];
    __shared__ float su [SCL][SWP];
    __shared__ float sz [SCL][SWP];
    __shared__ float sy [SCL][SWP];

    const int b    = blockIdx.y;
    const int d0   = blockIdx.x * SWP;
    const int tid  = threadIdx.x;
    const int w    = tid >> 5;
    const int lane = tid & 31;
    const int d    = d0 + w;
    const int mb   = b * LL;

    const float Aln = -__expf(A_log[d*DSTATE + lane]);
    const float Dd  = D_param[d];
    float h = 0.f;

    for (int c0 = 0; c0 < LL; c0 += SCL) {
        for (int idx = tid; idx < SCL*DSTATE; idx += 256) {
            int t = idx >> 5, n = idx & 31;
            int m = mb + c0 + t;
            sB[t][n] = dbl[(size_t)m*XPROJ_N + DTRANK + n];
            sC[t][n] = dbl[(size_t)m*XPROJ_N + DTRANK + DSTATE + n];
        }
        for (int idx = tid; idx < SCL*SWP; idx += 256) {
            int t = idx >> 3, dd = idx & 7;
            int m = mb + c0 + t;
            sdt[t][dd] = dt[(size_t)m*DINNER + d0 + dd];
            su [t][dd] = uc[(size_t)m*DINNER + d0 + dd];
            sz [t][dd] = xz[(size_t)m*(2*DINNER) + DINNER + d0 + dd];
        }
        __syncthreads();

        #pragma unroll 4
        for (int t = 0; t < SCL; ++t) {
            float dtv = sdt[t][w];
            float uv  = su[t][w];
            float dA  = __expf(dtv * Aln);
            h = fmaf(dA, h, (dtv * uv) * sB[t][lane]);
            float p = h * sC[t][lane];
            p += __shfl_xor_sync(0xffffffffu, p, 16);
            p += __shfl_xor_sync(0xffffffffu, p, 8);
            p += __shfl_xor_sync(0xffffffffu, p, 4);
            p += __shfl_xor_sync(0xffffffffu, p, 2);
            p += __shfl_xor_sync(0xffffffffu, p, 1);
            if (lane == 0) {
                float yv = p + uv * Dd;
                float zv = sz[t][w];
                sy[t][w] = yv * (zv / (1.f + __expf(-zv)));
            }
        }
        __syncthreads();

        for (int idx = tid; idx < SCL*SWP; idx += 256) {
            int t = idx >> 3, dd = idx & 7;
            y[(size_t)(mb + c0 + t)*DINNER + d0 + dd] = sy[t][dd];
        }
    }
}

// ---------------- Launch ----------------
extern "C" void kernel_launch(void* const* d_in, const int* in_sizes, int n_in,
                              void* d_out, int out_size)
{
    const float* x         = (const float*)d_in[0];
    const float* norm_w    = (const float*)d_in[1];
    const float* in_proj_w = (const float*)d_in[2];
    const float* conv_w    = (const float*)d_in[3];
    const float* conv_b    = (const float*)d_in[4];
    const float* x_proj_w  = (const float*)d_in[5];
    const float* dt_proj_w = (const float*)d_in[6];
    const float* dt_proj_b = (const float*)d_in[7];
    const float* A_log     = (const float*)d_in[8];
    const float* D_param   = (const float*)d_in[9];
    const float* out_proj_w= (const float*)d_in[10];
    float* out = (float*)d_out;

    float *p_xn, *p_xz, *p_uc, *p_dbl, *p_dt, *p_y;
    cudaGetSymbolAddress((void**)&p_xn,  g_xn);
    cudaGetSymbolAddress((void**)&p_xz,  g_xz);
    cudaGetSymbolAddress((void**)&p_uc,  g_uc);
    cudaGetSymbolAddress((void**)&p_dbl, g_dbl);
    cudaGetSymbolAddress((void**)&p_dt,  g_dt);
    cudaGetSymbolAddress((void**)&p_y,   g_y);
    cudaFuncSetAttribute(mma_gemm<4,0>, cudaFuncAttributeMaxDynamicSharedMemorySize, SMEM_MT4);
    cudaFuncSetAttribute(mma_gemm<1,0>, cudaFuncAttributeMaxDynamicSharedMemorySize, SMEM_MT1);
    cudaFuncSetAttribute(mma_gemm<4,1>, cudaFuncAttributeMaxDynamicSharedMemorySize, SMEM_MT4);
    cudaFuncSetAttribute(mma_gemm<4,2>, cudaFuncAttributeMaxDynamicSharedMemorySize, SMEM_MT4);

    // 1) RMSNorm
    rmsnorm_kernel<<<MM, 256>>>(x, norm_w, p_xn);

    // 2) in_proj: xz[8192,4096] = xn @ in_proj_w^T
    mma_gemm<4,0><<<dim3((2*DINNER)/128, MM/128), 256, SMEM_MT4>>>(
        p_xn, DMODEL, in_proj_w, p_xz, 2*DINNER, DMODEL, nullptr, nullptr);

    // 3) conv + silu
    conv_silu_kernel<<<(MM*DINNER)/256, 256>>>(p_xz, conv_w, conv_b, p_uc);

    // 4) x_proj: dbl[8192,128] = uc @ x_proj_w^T  (BM=32 -> 256 CTAs, fills chip)
    mma_gemm<1,0><<<dim3(XPROJ_N/128, MM/32), 256, SMEM_MT1>>>(
        p_uc, DINNER, x_proj_w, p_dbl, XPROJ_N, DINNER, nullptr, nullptr);

    // 5) dt_proj + softplus (A = first 64 cols of dbl, lda=128)
    mma_gemm<4,1><<<dim3(DINNER/128, MM/128), 256, SMEM_MT4>>>(
        p_dbl, XPROJ_N, dt_proj_w, p_dt, DINNER, DTRANK, dt_proj_b, nullptr);

    // 6) selective scan + skip + gate
    scan_kernel<<<dim3(DINNER/SWP, BB), 256>>>(
        p_xz, p_uc, p_dbl, p_dt, A_log, D_param, p_y);

    // 7) out_proj + residual
    mma_gemm<4,2><<<dim3(DMODEL/128, MM/128), 256, SMEM_MT4>>>(
        p_y, DINNER, out_proj_w, out, DMODEL, DINNER, nullptr, x);
}